// round 12
// baseline (speedup 1.0000x reference)
#include <cuda_runtime.h>
#include <cuda_fp16.h>
#include <cstdint>
#include <mma.h>

using namespace nvcuda;

// ---------------------------------------------------------------------------
// MoE HyperModel, round 11:
//  - k_fused: k_base (fast R10 version) + fp32->fp16 weight converts in ONE
//    launch (block-role dispatch) so converts overlap base across SMs.
//  - GEMMs: R9's cp.async fp16 3-stage ring (the fast variant).
//  - k_z: float4-vectorized.
// ---------------------------------------------------------------------------

namespace {
constexpr int kEMB = 1024;
constexpr int kCTX = 32;
constexpr int kNE  = 16;
constexpr int kH1  = 2048;
constexpr int kH2  = 512;
constexpr int kB   = 8;
constexpr int kM   = kCTX * kB;     // 256
constexpr int kFO  = 16384;
constexpr int kW1R = kEMB + kCTX;   // 1056

constexpr int kLDAh = 72;    // smem A stride (halves): 256 rows x 64 k (+pad)
constexpr int kLDBh = 136;   // smem B stride (halves): 64 rows x 128 n (+pad)
constexpr int kAstH = 256 * kLDAh;        // 18432 halves
constexpr int kBstH = 64 * kLDBh;         // 8704 halves
constexpr int kStH  = kAstH + kBstH;      // 27136 halves
constexpr int kSmemGemm = 3 * kStH * 2;   // 162816 bytes

// fused-kernel block ranges
constexpr int kBaseBlocks = (kH1 / 256) * (kNE + 1);            // 136
constexpr int kW2Elems = kNE * kH1 * kH2;                       // 16,777,216
constexpr int kWOElems = kH2 * kFO;                             //  8,388,608
constexpr int kW2Blocks = kW2Elems / 2048;                      // 8192
constexpr int kWOBlocks = kWOElems / 2048;                      // 4096
constexpr int kFusedBlocks = kBaseBlocks + kW2Blocks + 2 * kWOBlocks;  // 16520
}

// Scratch (static device arrays -- allocation-free).
__device__ float  g_g1[kB * kH1];
__device__ float  g_w[kB * kNE];
__device__ float  g_base[kNE * kB * kH1];
__device__ float  g_eo2[(size_t)2 * kNE * kM * kH2];   // split-K partials
__device__ __half g_zh[kM * kH2];                      // z in fp16
__device__ __half g_W2h[(size_t)kW2Elems];             // 33.5 MB
__device__ __half g_WAh[(size_t)kWOElems];             // 16.8 MB
__device__ __half g_WBh[(size_t)kWOElems];             // 16.8 MB

// --------------------------- cp.async helpers ------------------------------
__device__ __forceinline__ void cp_async16(void* smem_dst, const void* gmem_src) {
    unsigned int s = (unsigned int)__cvta_generic_to_shared(smem_dst);
    asm volatile("cp.async.cg.shared.global [%0], [%1], 16;\n" :: "r"(s), "l"(gmem_src));
}
__device__ __forceinline__ void cp_commit() {
    asm volatile("cp.async.commit_group;\n");
}
template <int N>
__device__ __forceinline__ void cp_wait() {
    asm volatile("cp.async.wait_group %0;\n" :: "n"(N));
}

// --------------------------- stage loaders (fp16 sources) ------------------
// B: 64 k-rows x 128 n halves via cp.async (B pre-offset to n0). 4 chunks/thr.
__device__ __forceinline__ void load_B(__half* Bs, const __half* B, int ldb,
                                       int kt, int t)
{
#pragma unroll
    for (int i = 0; i < 4; i++) {
        const int id = t + i * 256;
        const int r = id >> 4, c8 = (id & 15) * 8;
        cp_async16(Bs + r * kLDBh + c8, B + (size_t)(kt + r) * ldb + c8);
    }
}
// A (out GEMM): 256 rows x 64 k halves via cp.async from g_zh. 8 chunks/thr.
__device__ __forceinline__ void load_A_cp(__half* As, const __half* A, int lda,
                                          int kt, int t)
{
#pragma unroll
    for (int i = 0; i < 8; i++) {
        const int id = t + i * 256;
        const int m = id >> 3, kc = (id & 7) * 8;
        cp_async16(As + m * kLDAh + kc, A + (size_t)m * lda + kt + kc);
    }
}
// A (eo GEMM, fused h): half( w[b] * relu(base[b][k] + W1c[c][k]) ), STS.
__device__ __forceinline__ void load_A_eo(__half* As,
                                          const float* base_e, const float* w1c_e,
                                          const float* ws, int kt, int t)
{
#pragma unroll
    for (int i = 0; i < 8; i++) {
        const int id = t + i * 256;
        const int m = id >> 3, kc = (id & 7) * 8;
        const int b = m & 7, c = m >> 3;
        const float* bp = base_e + (size_t)b * kH1 + kt + kc;
        const float* wp = w1c_e  + (size_t)c * kH1 + kt + kc;
        const float4 b0 = *reinterpret_cast<const float4*>(bp);
        const float4 b1 = *reinterpret_cast<const float4*>(bp + 4);
        const float4 w0 = *reinterpret_cast<const float4*>(wp);
        const float4 w1 = *reinterpret_cast<const float4*>(wp + 4);
        const float w = ws[b];
        __half2 h0 = __floats2half2_rn(w * fmaxf(b0.x + w0.x, 0.f), w * fmaxf(b0.y + w0.y, 0.f));
        __half2 h1 = __floats2half2_rn(w * fmaxf(b0.z + w0.z, 0.f), w * fmaxf(b0.w + w0.w, 0.f));
        __half2 h2 = __floats2half2_rn(w * fmaxf(b1.x + w1.x, 0.f), w * fmaxf(b1.y + w1.y, 0.f));
        __half2 h3 = __floats2half2_rn(w * fmaxf(b1.z + w1.z, 0.f), w * fmaxf(b1.w + w1.w, 0.f));
        uint4 v;
        v.x = *reinterpret_cast<unsigned*>(&h0);
        v.y = *reinterpret_cast<unsigned*>(&h1);
        v.z = *reinterpret_cast<unsigned*>(&h2);
        v.w = *reinterpret_cast<unsigned*>(&h3);
        *reinterpret_cast<uint4*>(As + m * kLDAh + kc) = v;
    }
}

// --------------------------- compute: warp 64x64, k-tile 64 ----------------
__device__ __forceinline__ void tile_compute(
    const __half* As, const __half* Bs, int wm, int wn,
    wmma::fragment<wmma::accumulator, 16, 16, 16, float> (&acc)[4][4])
{
#pragma unroll
    for (int kk = 0; kk < 4; kk++) {
        wmma::fragment<wmma::matrix_b, 16, 16, 16, __half, wmma::row_major> bf[4];
#pragma unroll
        for (int j = 0; j < 4; j++)
            wmma::load_matrix_sync(bf[j], Bs + (kk * 16) * kLDBh + wn * 64 + j * 16, kLDBh);
#pragma unroll
        for (int i = 0; i < 4; i++) {
            wmma::fragment<wmma::matrix_a, 16, 16, 16, __half, wmma::row_major> af;
            wmma::load_matrix_sync(af, As + (wm * 64 + i * 16) * kLDAh + kk * 16, kLDAh);
#pragma unroll
            for (int j = 0; j < 4; j++)
                wmma::mma_sync(acc[i][j], af, bf[j], acc[i][j]);
        }
    }
}

// ---------------------------------------------------------------------------
// k_fused: block-role dispatch.
//   bid < 136                : k_base role (e = bid>>3, jtile = bid&7)
//   next 8192 blocks         : convert W2  fp32 -> g_W2h
//   next 4096 blocks         : convert WA  -> g_WAh
//   next 4096 blocks         : convert WB  -> g_WBh
// ---------------------------------------------------------------------------
__global__ __launch_bounds__(256) void k_fused(
    const float* __restrict__ s,
    const float* __restrict__ W1, const float* __restrict__ b1,
    const float* __restrict__ Wg1, const float* __restrict__ bg1,
    const float* __restrict__ W2,
    const float* __restrict__ WA, const float* __restrict__ WB)
{
    const int bid = blockIdx.x;
    const int t = threadIdx.x;

    if (bid >= kBaseBlocks) {
        // ---- convert role ----
        const int cb = bid - kBaseBlocks;
        const float* src;
        __half* dst;
        int loc;
        if (cb < kW2Blocks)      { src = W2; dst = g_W2h; loc = cb; }
        else if (cb < kW2Blocks + kWOBlocks) { src = WA; dst = g_WAh; loc = cb - kW2Blocks; }
        else                     { src = WB; dst = g_WBh; loc = cb - kW2Blocks - kWOBlocks; }
        const size_t i = ((size_t)loc * 256 + t) * 8;
        const float4 a = *reinterpret_cast<const float4*>(src + i);
        const float4 b = *reinterpret_cast<const float4*>(src + i + 4);
        __half2 h0 = __floats2half2_rn(a.x, a.y);
        __half2 h1 = __floats2half2_rn(a.z, a.w);
        __half2 h2 = __floats2half2_rn(b.x, b.y);
        __half2 h3 = __floats2half2_rn(b.z, b.w);
        uint4 v;
        v.x = *reinterpret_cast<unsigned*>(&h0);
        v.y = *reinterpret_cast<unsigned*>(&h1);
        v.z = *reinterpret_cast<unsigned*>(&h2);
        v.w = *reinterpret_cast<unsigned*>(&h3);
        *reinterpret_cast<uint4*>(dst + i) = v;
        return;
    }

    // ---- base role ----
    __shared__ float sh[kB * kEMB];   // 32 KB: s, then reduction buffer
    const int e = bid >> 3;
    const int jt = bid & 7;
    const int q = t & 63;
    const int slice = t >> 6;
    const int j = jt * 256 + q * 4;

    for (int i = t; i < kB * kEMB; i += 256) sh[i] = s[i];
    __syncthreads();

    const float* __restrict__ W = (e < kNE) ? (W1 + (size_t)e * kW1R * kH1) : Wg1;

    float acc[kB][4];
#pragma unroll
    for (int b = 0; b < kB; b++)
#pragma unroll
        for (int c = 0; c < 4; c++) acc[b][c] = 0.f;

    const int i0 = slice * 256;
#pragma unroll 8
    for (int i = i0; i < i0 + 256; i++) {
        const float4 wv = *reinterpret_cast<const float4*>(W + (size_t)i * kH1 + j);
#pragma unroll
        for (int b = 0; b < kB; b++) {
            const float sv = sh[b * kEMB + i];
            acc[b][0] += sv * wv.x;
            acc[b][1] += sv * wv.y;
            acc[b][2] += sv * wv.z;
            acc[b][3] += sv * wv.w;
        }
    }

    __syncthreads();
    if (slice > 0) {
#pragma unroll
        for (int b = 0; b < kB; b++)
#pragma unroll
            for (int c = 0; c < 4; c++)
                sh[(b * 4 + c) * 192 + (slice - 1) * 64 + q] = acc[b][c];
    }
    __syncthreads();
    if (slice == 0) {
#pragma unroll
        for (int sl = 0; sl < 3; sl++)
#pragma unroll
            for (int b = 0; b < kB; b++)
#pragma unroll
                for (int c = 0; c < 4; c++)
                    acc[b][c] += sh[(b * 4 + c) * 192 + sl * 64 + q];

        if (e < kNE) {
            const float4 bias = *reinterpret_cast<const float4*>(b1 + e * kH1 + j);
#pragma unroll
            for (int b = 0; b < kB; b++) {
                float4 o;
                o.x = acc[b][0] + bias.x; o.y = acc[b][1] + bias.y;
                o.z = acc[b][2] + bias.z; o.w = acc[b][3] + bias.w;
                *reinterpret_cast<float4*>(&g_base[((size_t)e * kB + b) * kH1 + j]) = o;
            }
        } else {
            const float4 bias = *reinterpret_cast<const float4*>(bg1 + j);
#pragma unroll
            for (int b = 0; b < kB; b++) {
                float4 o;
                o.x = fmaxf(acc[b][0] + bias.x, 0.f);
                o.y = fmaxf(acc[b][1] + bias.y, 0.f);
                o.z = fmaxf(acc[b][2] + bias.z, 0.f);
                o.w = fmaxf(acc[b][3] + bias.w, 0.f);
                *reinterpret_cast<float4*>(&g_g1[b * kH1 + j]) = o;
            }
        }
    }
}

// ---------------------------------------------------------------------------
// k_gate
// ---------------------------------------------------------------------------
__global__ __launch_bounds__(1024) void k_gate(
    const float* __restrict__ Wg2, const float* __restrict__ bg2)
{
    __shared__ float red[1024];
    const int t = threadIdx.x;
    const int b = t >> 7;
    const int rem = t & 127;
    const int kc = rem >> 4;
    const int x = rem & 15;

    float acc = 0.f;
    const int j0 = kc * 256;
#pragma unroll 4
    for (int j = j0; j < j0 + 256; j++)
        acc += g_g1[b * kH1 + j] * Wg2[j * kNE + x];
    red[t] = acc;
    __syncthreads();

    if (t < 128) {
        const int bb = t >> 4;
        const int xx = t & 15;
        float a = bg2[xx];
#pragma unroll
        for (int k = 0; k < 8; k++) a += red[bb * 128 + k * 16 + xx];

        float mx = a;
#pragma unroll
        for (int o = 8; o >= 1; o >>= 1)
            mx = fmaxf(mx, __shfl_xor_sync(0xffffffffu, mx, o, 16));
        const float ev = expf(a - mx);
        float sm = ev;
#pragma unroll
        for (int o = 8; o >= 1; o >>= 1)
            sm += __shfl_xor_sync(0xffffffffu, sm, o, 16);

        g_w[bb * kNE + xx] = ev / sm;
    }
}

// ---------------------------------------------------------------------------
// k_gemm_eo: fused-h split-K per-expert fp16 GEMM, tile 256x128, k-tile 64,
// 3-stage ring (B via cp.async from g_W2h, A computed + STS).
// Grid: (4 ntiles, 1, 32 = expert*2 + khalf). K per CTA = 1024, 16 k-tiles.
// ---------------------------------------------------------------------------
__global__ __launch_bounds__(256) void k_gemm_eo(
    const float* __restrict__ W1)
{
    extern __shared__ __align__(16) char smem_raw[];
    __half* smem = reinterpret_cast<__half*>(smem_raw);
    __shared__ float ws[kB];

    const int t = threadIdx.x;
    const int warp = t >> 5;
    const int wm = warp >> 1;   // 0..3
    const int wn = warp & 1;    // 0..1
    const int zz = blockIdx.z, e = zz >> 1, kh = zz & 1;
    const int n0 = blockIdx.x * 128;

    if (t < kB) ws[t] = g_w[t * kNE + e];

    const float* base_e = g_base + (size_t)e * kB * kH1 + kh * 1024;
    const float* w1c_e  = W1 + ((size_t)e * kW1R + kEMB) * kH1 + kh * 1024;
    const __half* B     = g_W2h + (size_t)e * kH1 * kH2 + (size_t)(kh * 1024) * kH2 + n0;

    wmma::fragment<wmma::accumulator, 16, 16, 16, float> acc[4][4];
#pragma unroll
    for (int i = 0; i < 4; i++)
#pragma unroll
        for (int j = 0; j < 4; j++) wmma::fill_fragment(acc[i][j], 0.f);

    __syncthreads();   // ws visible

    constexpr int NT = 1024 / 64;   // 16
    load_B(smem + kAstH, B, kH2, 0, t);
    cp_commit();
    load_A_eo(smem, base_e, w1c_e, ws, 0, t);
    load_B(smem + kStH + kAstH, B, kH2, 64, t);
    cp_commit();
    load_A_eo(smem + kStH, base_e, w1c_e, ws, 64, t);
    __syncthreads();

    for (int it = 0; it < NT; it++) {
        if (it + 1 < NT) cp_wait<1>(); else cp_wait<0>();
        __syncthreads();
        if (it + 2 < NT) {
            __half* nxt = smem + ((it + 2) % 3) * kStH;
            load_B(nxt + kAstH, B, kH2, (it + 2) * 64, t);
            cp_commit();
            load_A_eo(nxt, base_e, w1c_e, ws, (it + 2) * 64, t);
        }
        const __half* stg = smem + (it % 3) * kStH;
        tile_compute(stg, stg + kAstH, wm, wn, acc);
    }

    float* O = g_eo2 + (size_t)zz * kM * kH2 + n0;
#pragma unroll
    for (int i = 0; i < 4; i++)
#pragma unroll
        for (int j = 0; j < 4; j++)
            wmma::store_matrix_sync(O + (size_t)(wm * 64 + i * 16) * kH2 + wn * 64 + j * 16,
                                    acc[i][j], kH2, wmma::mem_row_major);
}

// ---------------------------------------------------------------------------
// k_z: z = half( sum over 32 partial slabs + sum_e w[b,e]*b2[e] ), float4.
// Grid 128 x 256; each thread handles 4 consecutive n.
// ---------------------------------------------------------------------------
__global__ __launch_bounds__(256) void k_z(const float* __restrict__ b2)
{
    const int idx4 = blockIdx.x * 256 + threadIdx.x;   // < 32768
    const int base = idx4 * 4;
    const int n = base & (kH2 - 1);
    const int m = base >> 9;
    const int b = m & 7;

    float4 acc = make_float4(0.f, 0.f, 0.f, 0.f);
#pragma unroll
    for (int p = 0; p < 2 * kNE; p++) {
        const float4 v = *reinterpret_cast<const float4*>(
            g_eo2 + (size_t)p * (kM * kH2) + base);
        acc.x += v.x; acc.y += v.y; acc.z += v.z; acc.w += v.w;
    }
#pragma unroll
    for (int e = 0; e < kNE; e++) {
        const float w = g_w[b * kNE + e];
        const float4 bv = *reinterpret_cast<const float4*>(b2 + e * kH2 + n);
        acc.x += w * bv.x; acc.y += w * bv.y; acc.z += w * bv.z; acc.w += w * bv.w;
    }
    __half2 h0 = __floats2half2_rn(acc.x, acc.y);
    __half2 h1 = __floats2half2_rn(acc.z, acc.w);
    uint2 v;
    v.x = *reinterpret_cast<unsigned*>(&h0);
    v.y = *reinterpret_cast<unsigned*>(&h1);
    *reinterpret_cast<uint2*>(g_zh + base) = v;
}

// ---------------------------------------------------------------------------
// k_gemm_out: z(256x512 fp16) @ {WAh,WBh}(512x16384 fp16) + bias -> out f32.
// Tile 256x128, 3-stage cp.async ring, 8 k-tiles of 64. Grid (128, 1, 2).
// ---------------------------------------------------------------------------
__global__ __launch_bounds__(256) void k_gemm_out(
    const float* __restrict__ bA, const float* __restrict__ bB,
    float* __restrict__ out)
{
    extern __shared__ __align__(16) char smem_raw[];
    __half* smem = reinterpret_cast<__half*>(smem_raw);

    const int t = threadIdx.x;
    const int warp = t >> 5;
    const int wm = warp >> 1;
    const int wn = warp & 1;
    const int mat = blockIdx.z;
    const int n0 = blockIdx.x * 128;

    const __half* Bw = (mat ? g_WBh : g_WAh) + n0;
    const float* bias = mat ? bB : bA;
    const __half* A = g_zh;

    wmma::fragment<wmma::accumulator, 16, 16, 16, float> acc[4][4];
#pragma unroll
    for (int i = 0; i < 4; i++)
#pragma unroll
        for (int j = 0; j < 4; j++) wmma::fill_fragment(acc[i][j], 0.f);

    constexpr int NT = kH2 / 64;   // 8
    load_A_cp(smem, A, kH2, 0, t);
    load_B(smem + kAstH, Bw, kFO, 0, t);
    cp_commit();
    load_A_cp(smem + kStH, A, kH2, 64, t);
    load_B(smem + kStH + kAstH, Bw, kFO, 64, t);
    cp_commit();

    for (int it = 0; it < NT; it++) {
        if (it + 1 < NT) cp_wait<1>(); else cp_wait<0>();
        __syncthreads();
        if (it + 2 < NT) {
            __half* nxt = smem + ((it + 2) % 3) * kStH;
            load_A_cp(nxt, A, kH2, (it + 2) * 64, t);
            load_B(nxt + kAstH, Bw, kFO, (it + 2) * 64, t);
            cp_commit();
        }
        const __half* stg = smem + (it % 3) * kStH;
        tile_compute(stg, stg + kAstH, wm, wn, acc);
    }

    // Epilogue: stage 256x128 fp32 (stride 132) in smem, add bias, stores.
    __syncthreads();
    float* stage = reinterpret_cast<float*>(smem_raw);   // 256*132*4 = 135168 B
#pragma unroll
    for (int i = 0; i < 4; i++)
#pragma unroll
        for (int j = 0; j < 4; j++)
            wmma::store_matrix_sync(stage + (wm * 64 + i * 16) * 132 + wn * 64 + j * 16,
                                    acc[i][j], 132, wmma::mem_row_major);
    __syncthreads();

    float* O = out + (size_t)mat * kM * kFO + n0;
#pragma unroll
    for (int i = 0; i < 32; i++) {
        const int id = t + i * 256;
        const int r = id >> 5, c4 = (id & 31) * 4;
        float4 v = *reinterpret_cast<const float4*>(stage + r * 132 + c4);
        const float4 bv = *reinterpret_cast<const float4*>(bias + n0 + c4);
        v.x += bv.x; v.y += bv.y; v.z += bv.z; v.w += bv.w;
        *reinterpret_cast<float4*>(O + (size_t)r * kFO + c4) = v;
    }
}

// ---------------------------------------------------------------------------
// kernel_launch
// ---------------------------------------------------------------------------
extern "C" void kernel_launch(void* const* d_in, const int* in_sizes, int n_in,
                              void* d_out, int out_size)
{
    const float* s   = (const float*)d_in[0];
    const float* Wg1 = (const float*)d_in[1];
    const float* bg1 = (const float*)d_in[2];
    const float* Wg2 = (const float*)d_in[3];
    const float* bg2 = (const float*)d_in[4];
    const float* W1  = (const float*)d_in[5];
    const float* b1  = (const float*)d_in[6];
    const float* W2  = (const float*)d_in[7];
    const float* b2  = (const float*)d_in[8];
    const float* WA  = (const float*)d_in[9];
    const float* bA  = (const float*)d_in[10];
    const float* WB  = (const float*)d_in[11];
    const float* bB  = (const float*)d_in[12];
    float* out = (float*)d_out;

    cudaFuncSetAttribute(k_gemm_eo,  cudaFuncAttributeMaxDynamicSharedMemorySize, kSmemGemm);
    cudaFuncSetAttribute(k_gemm_out, cudaFuncAttributeMaxDynamicSharedMemorySize, kSmemGemm);

    k_fused<<<kFusedBlocks, 256>>>(s, W1, b1, Wg1, bg1, W2, WA, WB);
    k_gate<<<1, 1024>>>(Wg2, bg2);
    k_gemm_eo<<<dim3(kH2 / 128, 1, 2 * kNE), 256, kSmemGemm>>>(W1);
    k_z<<<(kM * kH2 / 4) / 256, 256>>>(b2);
    k_gemm_out<<<dim3(kFO / 128, 1, 2), 256, kSmemGemm>>>(bA, bB, out);
}

// round 13
// speedup vs baseline: 1.1320x; 1.1320x over previous
#include <cuda_runtime.h>
#include <cuda_fp16.h>
#include <cstdint>
#include <mma.h>

using namespace nvcuda;

// ---------------------------------------------------------------------------
// MoE HyperModel, round 12: 2-CTA/SM GEMMs.
//  - GEMM tiles 128x128 (warp 32x64, 8 warps), 3-stage cp.async ring,
//    __launch_bounds__(256,2): two CTAs per SM interleave sync bubbles.
//  - k_fused (base + weight converts) as R11; k_z scalar (fast variant).
// ---------------------------------------------------------------------------

namespace {
constexpr int kEMB = 1024;
constexpr int kCTX = 32;
constexpr int kNE  = 16;
constexpr int kH1  = 2048;
constexpr int kH2  = 512;
constexpr int kB   = 8;
constexpr int kM   = kCTX * kB;     // 256
constexpr int kFO  = 16384;
constexpr int kW1R = kEMB + kCTX;   // 1056

constexpr int kLDAh = 72;    // smem A stride (halves): 128 rows x 64 k (+pad)
constexpr int kLDBh = 136;   // smem B stride (halves): 64 rows x 128 n (+pad)
constexpr int kAstH = 128 * kLDAh;        // 9216 halves
constexpr int kBstH = 64 * kLDBh;         // 8704 halves
constexpr int kStH  = kAstH + kBstH;      // 17920 halves
constexpr int kSmemGemm = 3 * kStH * 2;   // 107520 bytes (fits 2 CTAs/SM)

// fused-kernel block ranges
constexpr int kBaseBlocks = (kH1 / 256) * (kNE + 1);            // 136
constexpr int kW2Elems = kNE * kH1 * kH2;                       // 16,777,216
constexpr int kWOElems = kH2 * kFO;                             //  8,388,608
constexpr int kW2Blocks = kW2Elems / 2048;                      // 8192
constexpr int kWOBlocks = kWOElems / 2048;                      // 4096
constexpr int kFusedBlocks = kBaseBlocks + kW2Blocks + 2 * kWOBlocks;  // 16520
}

// Scratch (static device arrays -- allocation-free).
__device__ float  g_g1[kB * kH1];
__device__ float  g_w[kB * kNE];
__device__ float  g_base[kNE * kB * kH1];
__device__ float  g_eo2[(size_t)2 * kNE * kM * kH2];   // split-K partials
__device__ __half g_zh[kM * kH2];                      // z in fp16
__device__ __half g_W2h[(size_t)kW2Elems];             // 33.5 MB
__device__ __half g_WAh[(size_t)kWOElems];             // 16.8 MB
__device__ __half g_WBh[(size_t)kWOElems];             // 16.8 MB

// --------------------------- cp.async helpers ------------------------------
__device__ __forceinline__ void cp_async16(void* smem_dst, const void* gmem_src) {
    unsigned int s = (unsigned int)__cvta_generic_to_shared(smem_dst);
    asm volatile("cp.async.cg.shared.global [%0], [%1], 16;\n" :: "r"(s), "l"(gmem_src));
}
__device__ __forceinline__ void cp_commit() {
    asm volatile("cp.async.commit_group;\n");
}
template <int N>
__device__ __forceinline__ void cp_wait() {
    asm volatile("cp.async.wait_group %0;\n" :: "n"(N));
}

// --------------------------- stage loaders (fp16 sources) ------------------
// B: 64 k-rows x 128 n halves via cp.async (pre-offset to n0). 4 chunks/thr.
__device__ __forceinline__ void load_B(__half* Bs, const __half* B, int ldb,
                                       int kt, int t)
{
#pragma unroll
    for (int i = 0; i < 4; i++) {
        const int id = t + i * 256;
        const int r = id >> 4, c8 = (id & 15) * 8;
        cp_async16(Bs + r * kLDBh + c8, B + (size_t)(kt + r) * ldb + c8);
    }
}
// A (out GEMM): 128 rows x 64 k halves via cp.async (pre-offset to m0). 4/thr.
__device__ __forceinline__ void load_A_cp(__half* As, const __half* A, int lda,
                                          int kt, int t)
{
#pragma unroll
    for (int i = 0; i < 4; i++) {
        const int id = t + i * 256;
        const int m = id >> 3, kc = (id & 7) * 8;
        cp_async16(As + m * kLDAh + kc, A + (size_t)m * lda + kt + kc);
    }
}
// A (eo GEMM, fused h): half( w[b] * relu(base[b][k] + W1c[c][k]) ), STS.
__device__ __forceinline__ void load_A_eo(__half* As,
                                          const float* base_e, const float* w1c_e,
                                          const float* ws, int m0, int kt, int t)
{
#pragma unroll
    for (int i = 0; i < 4; i++) {
        const int id = t + i * 256;
        const int ml = id >> 3, kc = (id & 7) * 8;
        const int m = m0 + ml;
        const int b = m & 7, c = m >> 3;
        const float* bp = base_e + (size_t)b * kH1 + kt + kc;
        const float* wp = w1c_e  + (size_t)c * kH1 + kt + kc;
        const float4 b0 = *reinterpret_cast<const float4*>(bp);
        const float4 b1 = *reinterpret_cast<const float4*>(bp + 4);
        const float4 w0 = *reinterpret_cast<const float4*>(wp);
        const float4 w1 = *reinterpret_cast<const float4*>(wp + 4);
        const float w = ws[b];
        __half2 h0 = __floats2half2_rn(w * fmaxf(b0.x + w0.x, 0.f), w * fmaxf(b0.y + w0.y, 0.f));
        __half2 h1 = __floats2half2_rn(w * fmaxf(b0.z + w0.z, 0.f), w * fmaxf(b0.w + w0.w, 0.f));
        __half2 h2 = __floats2half2_rn(w * fmaxf(b1.x + w1.x, 0.f), w * fmaxf(b1.y + w1.y, 0.f));
        __half2 h3 = __floats2half2_rn(w * fmaxf(b1.z + w1.z, 0.f), w * fmaxf(b1.w + w1.w, 0.f));
        uint4 v;
        v.x = *reinterpret_cast<unsigned*>(&h0);
        v.y = *reinterpret_cast<unsigned*>(&h1);
        v.z = *reinterpret_cast<unsigned*>(&h2);
        v.w = *reinterpret_cast<unsigned*>(&h3);
        *reinterpret_cast<uint4*>(As + ml * kLDAh + kc) = v;
    }
}

// --------------------------- compute: warp 32x64, k-tile 64 ----------------
// 8 warps: wm = warp>>1 (4 m-slots of 32), wn = warp&1 (2 n-slots of 64).
__device__ __forceinline__ void tile_compute(
    const __half* As, const __half* Bs, int wm, int wn,
    wmma::fragment<wmma::accumulator, 16, 16, 16, float> (&acc)[2][4])
{
#pragma unroll
    for (int kk = 0; kk < 4; kk++) {
        wmma::fragment<wmma::matrix_b, 16, 16, 16, __half, wmma::row_major> bf[4];
#pragma unroll
        for (int j = 0; j < 4; j++)
            wmma::load_matrix_sync(bf[j], Bs + (kk * 16) * kLDBh + wn * 64 + j * 16, kLDBh);
#pragma unroll
        for (int i = 0; i < 2; i++) {
            wmma::fragment<wmma::matrix_a, 16, 16, 16, __half, wmma::row_major> af;
            wmma::load_matrix_sync(af, As + (wm * 32 + i * 16) * kLDAh + kk * 16, kLDAh);
#pragma unroll
            for (int j = 0; j < 4; j++)
                wmma::mma_sync(acc[i][j], af, bf[j], acc[i][j]);
        }
    }
}

// ---------------------------------------------------------------------------
// k_fused: base role (136 blocks) + weight-convert roles (16384 blocks).
// ---------------------------------------------------------------------------
__global__ __launch_bounds__(256) void k_fused(
    const float* __restrict__ s,
    const float* __restrict__ W1, const float* __restrict__ b1,
    const float* __restrict__ Wg1, const float* __restrict__ bg1,
    const float* __restrict__ W2,
    const float* __restrict__ WA, const float* __restrict__ WB)
{
    const int bid = blockIdx.x;
    const int t = threadIdx.x;

    if (bid >= kBaseBlocks) {
        const int cb = bid - kBaseBlocks;
        const float* src;
        __half* dst;
        int loc;
        if (cb < kW2Blocks)      { src = W2; dst = g_W2h; loc = cb; }
        else if (cb < kW2Blocks + kWOBlocks) { src = WA; dst = g_WAh; loc = cb - kW2Blocks; }
        else                     { src = WB; dst = g_WBh; loc = cb - kW2Blocks - kWOBlocks; }
        const size_t i = ((size_t)loc * 256 + t) * 8;
        const float4 a = *reinterpret_cast<const float4*>(src + i);
        const float4 b = *reinterpret_cast<const float4*>(src + i + 4);
        __half2 h0 = __floats2half2_rn(a.x, a.y);
        __half2 h1 = __floats2half2_rn(a.z, a.w);
        __half2 h2 = __floats2half2_rn(b.x, b.y);
        __half2 h3 = __floats2half2_rn(b.z, b.w);
        uint4 v;
        v.x = *reinterpret_cast<unsigned*>(&h0);
        v.y = *reinterpret_cast<unsigned*>(&h1);
        v.z = *reinterpret_cast<unsigned*>(&h2);
        v.w = *reinterpret_cast<unsigned*>(&h3);
        *reinterpret_cast<uint4*>(dst + i) = v;
        return;
    }

    // ---- base role ----
    __shared__ float sh[kB * kEMB];
    const int e = bid >> 3;
    const int jt = bid & 7;
    const int q = t & 63;
    const int slice = t >> 6;
    const int j = jt * 256 + q * 4;

    for (int i = t; i < kB * kEMB; i += 256) sh[i] = s[i];
    __syncthreads();

    const float* __restrict__ W = (e < kNE) ? (W1 + (size_t)e * kW1R * kH1) : Wg1;

    float acc[kB][4];
#pragma unroll
    for (int b = 0; b < kB; b++)
#pragma unroll
        for (int c = 0; c < 4; c++) acc[b][c] = 0.f;

    const int i0 = slice * 256;
#pragma unroll 8
    for (int i = i0; i < i0 + 256; i++) {
        const float4 wv = *reinterpret_cast<const float4*>(W + (size_t)i * kH1 + j);
#pragma unroll
        for (int b = 0; b < kB; b++) {
            const float sv = sh[b * kEMB + i];
            acc[b][0] += sv * wv.x;
            acc[b][1] += sv * wv.y;
            acc[b][2] += sv * wv.z;
            acc[b][3] += sv * wv.w;
        }
    }

    __syncthreads();
    if (slice > 0) {
#pragma unroll
        for (int b = 0; b < kB; b++)
#pragma unroll
            for (int c = 0; c < 4; c++)
                sh[(b * 4 + c) * 192 + (slice - 1) * 64 + q] = acc[b][c];
    }
    __syncthreads();
    if (slice == 0) {
#pragma unroll
        for (int sl = 0; sl < 3; sl++)
#pragma unroll
            for (int b = 0; b < kB; b++)
#pragma unroll
                for (int c = 0; c < 4; c++)
                    acc[b][c] += sh[(b * 4 + c) * 192 + sl * 64 + q];

        if (e < kNE) {
            const float4 bias = *reinterpret_cast<const float4*>(b1 + e * kH1 + j);
#pragma unroll
            for (int b = 0; b < kB; b++) {
                float4 o;
                o.x = acc[b][0] + bias.x; o.y = acc[b][1] + bias.y;
                o.z = acc[b][2] + bias.z; o.w = acc[b][3] + bias.w;
                *reinterpret_cast<float4*>(&g_base[((size_t)e * kB + b) * kH1 + j]) = o;
            }
        } else {
            const float4 bias = *reinterpret_cast<const float4*>(bg1 + j);
#pragma unroll
            for (int b = 0; b < kB; b++) {
                float4 o;
                o.x = fmaxf(acc[b][0] + bias.x, 0.f);
                o.y = fmaxf(acc[b][1] + bias.y, 0.f);
                o.z = fmaxf(acc[b][2] + bias.z, 0.f);
                o.w = fmaxf(acc[b][3] + bias.w, 0.f);
                *reinterpret_cast<float4*>(&g_g1[b * kH1 + j]) = o;
            }
        }
    }
}

// ---------------------------------------------------------------------------
// k_gate
// ---------------------------------------------------------------------------
__global__ __launch_bounds__(1024) void k_gate(
    const float* __restrict__ Wg2, const float* __restrict__ bg2)
{
    __shared__ float red[1024];
    const int t = threadIdx.x;
    const int b = t >> 7;
    const int rem = t & 127;
    const int kc = rem >> 4;
    const int x = rem & 15;

    float acc = 0.f;
    const int j0 = kc * 256;
#pragma unroll 4
    for (int j = j0; j < j0 + 256; j++)
        acc += g_g1[b * kH1 + j] * Wg2[j * kNE + x];
    red[t] = acc;
    __syncthreads();

    if (t < 128) {
        const int bb = t >> 4;
        const int xx = t & 15;
        float a = bg2[xx];
#pragma unroll
        for (int k = 0; k < 8; k++) a += red[bb * 128 + k * 16 + xx];

        float mx = a;
#pragma unroll
        for (int o = 8; o >= 1; o >>= 1)
            mx = fmaxf(mx, __shfl_xor_sync(0xffffffffu, mx, o, 16));
        const float ev = expf(a - mx);
        float sm = ev;
#pragma unroll
        for (int o = 8; o >= 1; o >>= 1)
            sm += __shfl_xor_sync(0xffffffffu, sm, o, 16);

        g_w[bb * kNE + xx] = ev / sm;
    }
}

// ---------------------------------------------------------------------------
// k_gemm_eo: fused-h split-K per-expert fp16 GEMM, tile 128x128, 2 CTAs/SM.
// Grid: (4 ntiles, 2 mtiles, 32 = expert*2 + khalf). 16 k-tiles of 64.
// ---------------------------------------------------------------------------
__global__ __launch_bounds__(256, 2) void k_gemm_eo(
    const float* __restrict__ W1)
{
    extern __shared__ __align__(16) char smem_raw[];
    __half* smem = reinterpret_cast<__half*>(smem_raw);
    __shared__ float ws[kB];

    const int t = threadIdx.x;
    const int warp = t >> 5;
    const int wm = warp >> 1;   // 0..3
    const int wn = warp & 1;    // 0..1
    const int zz = blockIdx.z, e = zz >> 1, kh = zz & 1;
    const int m0 = blockIdx.y * 128;
    const int n0 = blockIdx.x * 128;

    if (t < kB) ws[t] = g_w[t * kNE + e];

    const float* base_e = g_base + (size_t)e * kB * kH1 + kh * 1024;
    const float* w1c_e  = W1 + ((size_t)e * kW1R + kEMB) * kH1 + kh * 1024;
    const __half* B     = g_W2h + (size_t)e * kH1 * kH2 + (size_t)(kh * 1024) * kH2 + n0;

    wmma::fragment<wmma::accumulator, 16, 16, 16, float> acc[2][4];
#pragma unroll
    for (int i = 0; i < 2; i++)
#pragma unroll
        for (int j = 0; j < 4; j++) wmma::fill_fragment(acc[i][j], 0.f);

    __syncthreads();   // ws visible

    constexpr int NT = 1024 / 64;   // 16
    load_B(smem + kAstH, B, kH2, 0, t);
    cp_commit();
    load_A_eo(smem, base_e, w1c_e, ws, m0, 0, t);
    load_B(smem + kStH + kAstH, B, kH2, 64, t);
    cp_commit();
    load_A_eo(smem + kStH, base_e, w1c_e, ws, m0, 64, t);
    __syncthreads();

    for (int it = 0; it < NT; it++) {
        if (it + 1 < NT) cp_wait<1>(); else cp_wait<0>();
        __syncthreads();
        if (it + 2 < NT) {
            __half* nxt = smem + ((it + 2) % 3) * kStH;
            load_B(nxt + kAstH, B, kH2, (it + 2) * 64, t);
            cp_commit();
            load_A_eo(nxt, base_e, w1c_e, ws, m0, (it + 2) * 64, t);
        }
        const __half* stg = smem + (it % 3) * kStH;
        tile_compute(stg, stg + kAstH, wm, wn, acc);
    }

    float* O = g_eo2 + (size_t)zz * kM * kH2 + (size_t)m0 * kH2 + n0;
#pragma unroll
    for (int i = 0; i < 2; i++)
#pragma unroll
        for (int j = 0; j < 4; j++)
            wmma::store_matrix_sync(O + (size_t)(wm * 32 + i * 16) * kH2 + wn * 64 + j * 16,
                                    acc[i][j], kH2, wmma::mem_row_major);
}

// ---------------------------------------------------------------------------
// k_z: z = half( sum over 32 partial slabs + sum_e w[b,e]*b2[e] ).
// ---------------------------------------------------------------------------
__global__ __launch_bounds__(256) void k_z(const float* __restrict__ b2)
{
    const int idx = blockIdx.x * 256 + threadIdx.x;
    const int n = idx & (kH2 - 1);
    const int m = idx >> 9;
    const int b = m & 7;

    float acc = 0.f;
#pragma unroll
    for (int p = 0; p < 2 * kNE; p++)
        acc += g_eo2[(size_t)p * (kM * kH2) + idx];
#pragma unroll
    for (int e = 0; e < kNE; e++)
        acc += g_w[b * kNE + e] * b2[e * kH2 + n];
    g_zh[idx] = __float2half_rn(acc);
}

// ---------------------------------------------------------------------------
// k_gemm_out: z(256x512 fp16) @ {WAh,WBh}(512x16384 fp16) + bias -> out f32.
// Tile 128x128, 2 CTAs/SM, 8 k-tiles of 64. Grid (128, 2, 2).
// ---------------------------------------------------------------------------
__global__ __launch_bounds__(256, 2) void k_gemm_out(
    const float* __restrict__ bA, const float* __restrict__ bB,
    float* __restrict__ out)
{
    extern __shared__ __align__(16) char smem_raw[];
    __half* smem = reinterpret_cast<__half*>(smem_raw);

    const int t = threadIdx.x;
    const int warp = t >> 5;
    const int wm = warp >> 1;
    const int wn = warp & 1;
    const int mat = blockIdx.z;
    const int m0 = blockIdx.y * 128;
    const int n0 = blockIdx.x * 128;

    const __half* Bw = (mat ? g_WBh : g_WAh) + n0;
    const float* bias = mat ? bB : bA;
    const __half* A = g_zh + (size_t)m0 * kH2;

    wmma::fragment<wmma::accumulator, 16, 16, 16, float> acc[2][4];
#pragma unroll
    for (int i = 0; i < 2; i++)
#pragma unroll
        for (int j = 0; j < 4; j++) wmma::fill_fragment(acc[i][j], 0.f);

    constexpr int NT = kH2 / 64;   // 8
    load_A_cp(smem, A, kH2, 0, t);
    load_B(smem + kAstH, Bw, kFO, 0, t);
    cp_commit();
    load_A_cp(smem + kStH, A, kH2, 64, t);
    load_B(smem + kStH + kAstH, Bw, kFO, 64, t);
    cp_commit();

    for (int it = 0; it < NT; it++) {
        if (it + 1 < NT) cp_wait<1>(); else cp_wait<0>();
        __syncthreads();
        if (it + 2 < NT) {
            __half* nxt = smem + ((it + 2) % 3) * kStH;
            load_A_cp(nxt, A, kH2, (it + 2) * 64, t);
            load_B(nxt + kAstH, Bw, kFO, (it + 2) * 64, t);
            cp_commit();
        }
        const __half* stg = smem + (it % 3) * kStH;
        tile_compute(stg, stg + kAstH, wm, wn, acc);
    }

    // Epilogue: stage 128x128 fp32 (stride 132) in smem, add bias, stores.
    __syncthreads();
    float* stage = reinterpret_cast<float*>(smem_raw);   // 128*132*4 = 67584 B
#pragma unroll
    for (int i = 0; i < 2; i++)
#pragma unroll
        for (int j = 0; j < 4; j++)
            wmma::store_matrix_sync(stage + (wm * 32 + i * 16) * 132 + wn * 64 + j * 16,
                                    acc[i][j], 132, wmma::mem_row_major);
    __syncthreads();

    float* O = out + (size_t)mat * kM * kFO + (size_t)m0 * kFO + n0;
#pragma unroll
    for (int i = 0; i < 16; i++) {
        const int id = t + i * 256;
        const int r = id >> 5, c4 = (id & 31) * 4;
        float4 v = *reinterpret_cast<const float4*>(stage + r * 132 + c4);
        const float4 bv = *reinterpret_cast<const float4*>(bias + n0 + c4);
        v.x += bv.x; v.y += bv.y; v.z += bv.z; v.w += bv.w;
        *reinterpret_cast<float4*>(O + (size_t)r * kFO + c4) = v;
    }
}

// ---------------------------------------------------------------------------
// kernel_launch
// ---------------------------------------------------------------------------
extern "C" void kernel_launch(void* const* d_in, const int* in_sizes, int n_in,
                              void* d_out, int out_size)
{
    const float* s   = (const float*)d_in[0];
    const float* Wg1 = (const float*)d_in[1];
    const float* bg1 = (const float*)d_in[2];
    const float* Wg2 = (const float*)d_in[3];
    const float* bg2 = (const float*)d_in[4];
    const float* W1  = (const float*)d_in[5];
    const float* b1  = (const float*)d_in[6];
    const float* W2  = (const float*)d_in[7];
    const float* b2  = (const float*)d_in[8];
    const float* WA  = (const float*)d_in[9];
    const float* bA  = (const float*)d_in[10];
    const float* WB  = (const float*)d_in[11];
    const float* bB  = (const float*)d_in[12];
    float* out = (float*)d_out;

    cudaFuncSetAttribute(k_gemm_eo,  cudaFuncAttributeMaxDynamicSharedMemorySize, kSmemGemm);
    cudaFuncSetAttribute(k_gemm_out, cudaFuncAttributeMaxDynamicSharedMemorySize, kSmemGemm);

    k_fused<<<kFusedBlocks, 256>>>(s, W1, b1, Wg1, bg1, W2, WA, WB);
    k_gate<<<1, 1024>>>(Wg2, bg2);
    k_gemm_eo<<<dim3(kH2 / 128, 2, 2 * kNE), 256, kSmemGemm>>>(W1);
    k_z<<<(kM * kH2) / 256, 256>>>(b2);
    k_gemm_out<<<dim3(kFO / 128, 2, 2), 256, kSmemGemm>>>(bA, bB, out);
}

// round 14
// speedup vs baseline: 1.1590x; 1.0238x over previous
#include <cuda_runtime.h>
#include <cuda_fp16.h>
#include <cstdint>
#include <mma.h>

using namespace nvcuda;

// ---------------------------------------------------------------------------
// MoE HyperModel, round 13: R12 + WA/WB fp16 converts moved INTO the
// HMMA-bound eo GEMM launch (tail convert-role blocks ride its spare DRAM BW).
// k_fused keeps base + W2 convert only.
// ---------------------------------------------------------------------------

namespace {
constexpr int kEMB = 1024;
constexpr int kCTX = 32;
constexpr int kNE  = 16;
constexpr int kH1  = 2048;
constexpr int kH2  = 512;
constexpr int kB   = 8;
constexpr int kM   = kCTX * kB;     // 256
constexpr int kFO  = 16384;
constexpr int kW1R = kEMB + kCTX;   // 1056

constexpr int kLDAh = 72;    // smem A stride (halves): 128 rows x 64 k (+pad)
constexpr int kLDBh = 136;   // smem B stride (halves): 64 rows x 128 n (+pad)
constexpr int kAstH = 128 * kLDAh;        // 9216 halves
constexpr int kBstH = 64 * kLDBh;         // 8704 halves
constexpr int kStH  = kAstH + kBstH;      // 17920 halves
constexpr int kSmemGemm = 3 * kStH * 2;   // 107520 bytes (fits 2 CTAs/SM)

// k_fused block ranges (base + W2 convert only)
constexpr int kBaseBlocks = (kH1 / 256) * (kNE + 1);            // 136
constexpr int kW2Elems = kNE * kH1 * kH2;                       // 16,777,216
constexpr int kWOElems = kH2 * kFO;                             //  8,388,608
constexpr int kW2Blocks = kW2Elems / 2048;                      // 8192
constexpr int kFusedBlocks = kBaseBlocks + kW2Blocks;           // 8328

// eo-launch convert role: 1024 blocks x 16384 elems cover WA+WB (16.8M elems)
constexpr int kCvtZ = 128;               // extra z-slices, 8 blocks (4x2) each
}

// Scratch (static device arrays -- allocation-free).
__device__ float  g_g1[kB * kH1];
__device__ float  g_w[kB * kNE];
__device__ float  g_base[kNE * kB * kH1];
__device__ float  g_eo2[(size_t)2 * kNE * kM * kH2];   // split-K partials
__device__ __half g_zh[kM * kH2];                      // z in fp16
__device__ __half g_W2h[(size_t)kW2Elems];             // 33.5 MB
__device__ __half g_WAh[(size_t)kWOElems];             // 16.8 MB
__device__ __half g_WBh[(size_t)kWOElems];             // 16.8 MB

// --------------------------- cp.async helpers ------------------------------
__device__ __forceinline__ void cp_async16(void* smem_dst, const void* gmem_src) {
    unsigned int s = (unsigned int)__cvta_generic_to_shared(smem_dst);
    asm volatile("cp.async.cg.shared.global [%0], [%1], 16;\n" :: "r"(s), "l"(gmem_src));
}
__device__ __forceinline__ void cp_commit() {
    asm volatile("cp.async.commit_group;\n");
}
template <int N>
__device__ __forceinline__ void cp_wait() {
    asm volatile("cp.async.wait_group %0;\n" :: "n"(N));
}

// --------------------------- convert helper --------------------------------
__device__ __forceinline__ void cvt8(const float* __restrict__ src,
                                     __half* __restrict__ dst, size_t i)
{
    const float4 a = *reinterpret_cast<const float4*>(src + i);
    const float4 b = *reinterpret_cast<const float4*>(src + i + 4);
    __half2 h0 = __floats2half2_rn(a.x, a.y);
    __half2 h1 = __floats2half2_rn(a.z, a.w);
    __half2 h2 = __floats2half2_rn(b.x, b.y);
    __half2 h3 = __floats2half2_rn(b.z, b.w);
    uint4 v;
    v.x = *reinterpret_cast<unsigned*>(&h0);
    v.y = *reinterpret_cast<unsigned*>(&h1);
    v.z = *reinterpret_cast<unsigned*>(&h2);
    v.w = *reinterpret_cast<unsigned*>(&h3);
    *reinterpret_cast<uint4*>(dst + i) = v;
}

// --------------------------- stage loaders (fp16 sources) ------------------
__device__ __forceinline__ void load_B(__half* Bs, const __half* B, int ldb,
                                       int kt, int t)
{
#pragma unroll
    for (int i = 0; i < 4; i++) {
        const int id = t + i * 256;
        const int r = id >> 4, c8 = (id & 15) * 8;
        cp_async16(Bs + r * kLDBh + c8, B + (size_t)(kt + r) * ldb + c8);
    }
}
__device__ __forceinline__ void load_A_cp(__half* As, const __half* A, int lda,
                                          int kt, int t)
{
#pragma unroll
    for (int i = 0; i < 4; i++) {
        const int id = t + i * 256;
        const int m = id >> 3, kc = (id & 7) * 8;
        cp_async16(As + m * kLDAh + kc, A + (size_t)m * lda + kt + kc);
    }
}
__device__ __forceinline__ void load_A_eo(__half* As,
                                          const float* base_e, const float* w1c_e,
                                          const float* ws, int m0, int kt, int t)
{
#pragma unroll
    for (int i = 0; i < 4; i++) {
        const int id = t + i * 256;
        const int ml = id >> 3, kc = (id & 7) * 8;
        const int m = m0 + ml;
        const int b = m & 7, c = m >> 3;
        const float* bp = base_e + (size_t)b * kH1 + kt + kc;
        const float* wp = w1c_e  + (size_t)c * kH1 + kt + kc;
        const float4 b0 = *reinterpret_cast<const float4*>(bp);
        const float4 b1 = *reinterpret_cast<const float4*>(bp + 4);
        const float4 w0 = *reinterpret_cast<const float4*>(wp);
        const float4 w1 = *reinterpret_cast<const float4*>(wp + 4);
        const float w = ws[b];
        __half2 h0 = __floats2half2_rn(w * fmaxf(b0.x + w0.x, 0.f), w * fmaxf(b0.y + w0.y, 0.f));
        __half2 h1 = __floats2half2_rn(w * fmaxf(b0.z + w0.z, 0.f), w * fmaxf(b0.w + w0.w, 0.f));
        __half2 h2 = __floats2half2_rn(w * fmaxf(b1.x + w1.x, 0.f), w * fmaxf(b1.y + w1.y, 0.f));
        __half2 h3 = __floats2half2_rn(w * fmaxf(b1.z + w1.z, 0.f), w * fmaxf(b1.w + w1.w, 0.f));
        uint4 v;
        v.x = *reinterpret_cast<unsigned*>(&h0);
        v.y = *reinterpret_cast<unsigned*>(&h1);
        v.z = *reinterpret_cast<unsigned*>(&h2);
        v.w = *reinterpret_cast<unsigned*>(&h3);
        *reinterpret_cast<uint4*>(As + ml * kLDAh + kc) = v;
    }
}

// --------------------------- compute: warp 32x64, k-tile 64 ----------------
__device__ __forceinline__ void tile_compute(
    const __half* As, const __half* Bs, int wm, int wn,
    wmma::fragment<wmma::accumulator, 16, 16, 16, float> (&acc)[2][4])
{
#pragma unroll
    for (int kk = 0; kk < 4; kk++) {
        wmma::fragment<wmma::matrix_b, 16, 16, 16, __half, wmma::row_major> bf[4];
#pragma unroll
        for (int j = 0; j < 4; j++)
            wmma::load_matrix_sync(bf[j], Bs + (kk * 16) * kLDBh + wn * 64 + j * 16, kLDBh);
#pragma unroll
        for (int i = 0; i < 2; i++) {
            wmma::fragment<wmma::matrix_a, 16, 16, 16, __half, wmma::row_major> af;
            wmma::load_matrix_sync(af, As + (wm * 32 + i * 16) * kLDAh + kk * 16, kLDAh);
#pragma unroll
            for (int j = 0; j < 4; j++)
                wmma::mma_sync(acc[i][j], af, bf[j], acc[i][j]);
        }
    }
}

// ---------------------------------------------------------------------------
// k_fused: base role (136 blocks) + W2 convert role (8192 blocks).
// ---------------------------------------------------------------------------
__global__ __launch_bounds__(256) void k_fused(
    const float* __restrict__ s,
    const float* __restrict__ W1, const float* __restrict__ b1,
    const float* __restrict__ Wg1, const float* __restrict__ bg1,
    const float* __restrict__ W2)
{
    const int bid = blockIdx.x;
    const int t = threadIdx.x;

    if (bid >= kBaseBlocks) {
        const int cb = bid - kBaseBlocks;
        cvt8(W2, g_W2h, ((size_t)cb * 256 + t) * 8);
        return;
    }

    // ---- base role ----
    __shared__ float sh[kB * kEMB];
    const int e = bid >> 3;
    const int jt = bid & 7;
    const int q = t & 63;
    const int slice = t >> 6;
    const int j = jt * 256 + q * 4;

    for (int i = t; i < kB * kEMB; i += 256) sh[i] = s[i];
    __syncthreads();

    const float* __restrict__ W = (e < kNE) ? (W1 + (size_t)e * kW1R * kH1) : Wg1;

    float acc[kB][4];
#pragma unroll
    for (int b = 0; b < kB; b++)
#pragma unroll
        for (int c = 0; c < 4; c++) acc[b][c] = 0.f;

    const int i0 = slice * 256;
#pragma unroll 8
    for (int i = i0; i < i0 + 256; i++) {
        const float4 wv = *reinterpret_cast<const float4*>(W + (size_t)i * kH1 + j);
#pragma unroll
        for (int b = 0; b < kB; b++) {
            const float sv = sh[b * kEMB + i];
            acc[b][0] += sv * wv.x;
            acc[b][1] += sv * wv.y;
            acc[b][2] += sv * wv.z;
            acc[b][3] += sv * wv.w;
        }
    }

    __syncthreads();
    if (slice > 0) {
#pragma unroll
        for (int b = 0; b < kB; b++)
#pragma unroll
            for (int c = 0; c < 4; c++)
                sh[(b * 4 + c) * 192 + (slice - 1) * 64 + q] = acc[b][c];
    }
    __syncthreads();
    if (slice == 0) {
#pragma unroll
        for (int sl = 0; sl < 3; sl++)
#pragma unroll
            for (int b = 0; b < kB; b++)
#pragma unroll
                for (int c = 0; c < 4; c++)
                    acc[b][c] += sh[(b * 4 + c) * 192 + sl * 64 + q];

        if (e < kNE) {
            const float4 bias = *reinterpret_cast<const float4*>(b1 + e * kH1 + j);
#pragma unroll
            for (int b = 0; b < kB; b++) {
                float4 o;
                o.x = acc[b][0] + bias.x; o.y = acc[b][1] + bias.y;
                o.z = acc[b][2] + bias.z; o.w = acc[b][3] + bias.w;
                *reinterpret_cast<float4*>(&g_base[((size_t)e * kB + b) * kH1 + j]) = o;
            }
        } else {
            const float4 bias = *reinterpret_cast<const float4*>(bg1 + j);
#pragma unroll
            for (int b = 0; b < kB; b++) {
                float4 o;
                o.x = fmaxf(acc[b][0] + bias.x, 0.f);
                o.y = fmaxf(acc[b][1] + bias.y, 0.f);
                o.z = fmaxf(acc[b][2] + bias.z, 0.f);
                o.w = fmaxf(acc[b][3] + bias.w, 0.f);
                *reinterpret_cast<float4*>(&g_g1[b * kH1 + j]) = o;
            }
        }
    }
}

// ---------------------------------------------------------------------------
// k_gate
// ---------------------------------------------------------------------------
__global__ __launch_bounds__(1024) void k_gate(
    const float* __restrict__ Wg2, const float* __restrict__ bg2)
{
    __shared__ float red[1024];
    const int t = threadIdx.x;
    const int b = t >> 7;
    const int rem = t & 127;
    const int kc = rem >> 4;
    const int x = rem & 15;

    float acc = 0.f;
    const int j0 = kc * 256;
#pragma unroll 4
    for (int j = j0; j < j0 + 256; j++)
        acc += g_g1[b * kH1 + j] * Wg2[j * kNE + x];
    red[t] = acc;
    __syncthreads();

    if (t < 128) {
        const int bb = t >> 4;
        const int xx = t & 15;
        float a = bg2[xx];
#pragma unroll
        for (int k = 0; k < 8; k++) a += red[bb * 128 + k * 16 + xx];

        float mx = a;
#pragma unroll
        for (int o = 8; o >= 1; o >>= 1)
            mx = fmaxf(mx, __shfl_xor_sync(0xffffffffu, mx, o, 16));
        const float ev = expf(a - mx);
        float sm = ev;
#pragma unroll
        for (int o = 8; o >= 1; o >>= 1)
            sm += __shfl_xor_sync(0xffffffffu, sm, o, 16);

        g_w[bb * kNE + xx] = ev / sm;
    }
}

// ---------------------------------------------------------------------------
// k_gemm_eo: GEMM role (z < 32): fused-h split-K per-expert fp16 GEMM,
// tile 128x128, 2 CTAs/SM. Convert role (z >= 32): WA/WB fp32->fp16,
// 1024 blocks x 16384 elems, scheduled after the GEMM blocks (high z).
// Grid: (4, 2, 32 + kCvtZ).
// ---------------------------------------------------------------------------
__global__ __launch_bounds__(256, 2) void k_gemm_eo(
    const float* __restrict__ W1,
    const float* __restrict__ WA, const float* __restrict__ WB)
{
    extern __shared__ __align__(16) char smem_raw[];
    __half* smem = reinterpret_cast<__half*>(smem_raw);
    __shared__ float ws[kB];

    const int t = threadIdx.x;
    const int zz = blockIdx.z;

    if (zz >= 2 * kNE) {
        // ---- convert role: WA then WB, 16384 elems per block ----
        const int cb = (zz - 2 * kNE) * 8 + blockIdx.y * 4 + blockIdx.x;  // 0..1023
        const float* src = (cb < 512) ? WA : WB;
        __half* dst      = (cb < 512) ? g_WAh : g_WBh;
        const size_t base = (size_t)(cb & 511) * 16384;
#pragma unroll
        for (int i = 0; i < 8; i++)
            cvt8(src, dst, base + (size_t)i * 2048 + t * 8);
        return;
    }

    const int warp = t >> 5;
    const int wm = warp >> 1;   // 0..3
    const int wn = warp & 1;    // 0..1
    const int e = zz >> 1, kh = zz & 1;
    const int m0 = blockIdx.y * 128;
    const int n0 = blockIdx.x * 128;

    if (t < kB) ws[t] = g_w[t * kNE + e];

    const float* base_e = g_base + (size_t)e * kB * kH1 + kh * 1024;
    const float* w1c_e  = W1 + ((size_t)e * kW1R + kEMB) * kH1 + kh * 1024;
    const __half* B     = g_W2h + (size_t)e * kH1 * kH2 + (size_t)(kh * 1024) * kH2 + n0;

    wmma::fragment<wmma::accumulator, 16, 16, 16, float> acc[2][4];
#pragma unroll
    for (int i = 0; i < 2; i++)
#pragma unroll
        for (int j = 0; j < 4; j++) wmma::fill_fragment(acc[i][j], 0.f);

    __syncthreads();   // ws visible

    constexpr int NT = 1024 / 64;   // 16
    load_B(smem + kAstH, B, kH2, 0, t);
    cp_commit();
    load_A_eo(smem, base_e, w1c_e, ws, m0, 0, t);
    load_B(smem + kStH + kAstH, B, kH2, 64, t);
    cp_commit();
    load_A_eo(smem + kStH, base_e, w1c_e, ws, m0, 64, t);
    __syncthreads();

    for (int it = 0; it < NT; it++) {
        if (it + 1 < NT) cp_wait<1>(); else cp_wait<0>();
        __syncthreads();
        if (it + 2 < NT) {
            __half* nxt = smem + ((it + 2) % 3) * kStH;
            load_B(nxt + kAstH, B, kH2, (it + 2) * 64, t);
            cp_commit();
            load_A_eo(nxt, base_e, w1c_e, ws, m0, (it + 2) * 64, t);
        }
        const __half* stg = smem + (it % 3) * kStH;
        tile_compute(stg, stg + kAstH, wm, wn, acc);
    }

    float* O = g_eo2 + (size_t)zz * kM * kH2 + (size_t)m0 * kH2 + n0;
#pragma unroll
    for (int i = 0; i < 2; i++)
#pragma unroll
        for (int j = 0; j < 4; j++)
            wmma::store_matrix_sync(O + (size_t)(wm * 32 + i * 16) * kH2 + wn * 64 + j * 16,
                                    acc[i][j], kH2, wmma::mem_row_major);
}

// ---------------------------------------------------------------------------
// k_z: z = half( sum over 32 partial slabs + sum_e w[b,e]*b2[e] ).
// ---------------------------------------------------------------------------
__global__ __launch_bounds__(256) void k_z(const float* __restrict__ b2)
{
    const int idx = blockIdx.x * 256 + threadIdx.x;
    const int n = idx & (kH2 - 1);
    const int m = idx >> 9;
    const int b = m & 7;

    float acc = 0.f;
#pragma unroll
    for (int p = 0; p < 2 * kNE; p++)
        acc += g_eo2[(size_t)p * (kM * kH2) + idx];
#pragma unroll
    for (int e = 0; e < kNE; e++)
        acc += g_w[b * kNE + e] * b2[e * kH2 + n];
    g_zh[idx] = __float2half_rn(acc);
}

// ---------------------------------------------------------------------------
// k_gemm_out: z(256x512 fp16) @ {WAh,WBh}(512x16384 fp16) + bias -> out f32.
// Tile 128x128, 2 CTAs/SM, 8 k-tiles of 64. Grid (128, 2, 2).
// ---------------------------------------------------------------------------
__global__ __launch_bounds__(256, 2) void k_gemm_out(
    const float* __restrict__ bA, const float* __restrict__ bB,
    float* __restrict__ out)
{
    extern __shared__ __align__(16) char smem_raw[];
    __half* smem = reinterpret_cast<__half*>(smem_raw);

    const int t = threadIdx.x;
    const int warp = t >> 5;
    const int wm = warp >> 1;
    const int wn = warp & 1;
    const int mat = blockIdx.z;
    const int m0 = blockIdx.y * 128;
    const int n0 = blockIdx.x * 128;

    const __half* Bw = (mat ? g_WBh : g_WAh) + n0;
    const float* bias = mat ? bB : bA;
    const __half* A = g_zh + (size_t)m0 * kH2;

    wmma::fragment<wmma::accumulator, 16, 16, 16, float> acc[2][4];
#pragma unroll
    for (int i = 0; i < 2; i++)
#pragma unroll
        for (int j = 0; j < 4; j++) wmma::fill_fragment(acc[i][j], 0.f);

    constexpr int NT = kH2 / 64;   // 8
    load_A_cp(smem, A, kH2, 0, t);
    load_B(smem + kAstH, Bw, kFO, 0, t);
    cp_commit();
    load_A_cp(smem + kStH, A, kH2, 64, t);
    load_B(smem + kStH + kAstH, Bw, kFO, 64, t);
    cp_commit();

    for (int it = 0; it < NT; it++) {
        if (it + 1 < NT) cp_wait<1>(); else cp_wait<0>();
        __syncthreads();
        if (it + 2 < NT) {
            __half* nxt = smem + ((it + 2) % 3) * kStH;
            load_A_cp(nxt, A, kH2, (it + 2) * 64, t);
            load_B(nxt + kAstH, Bw, kFO, (it + 2) * 64, t);
            cp_commit();
        }
        const __half* stg = smem + (it % 3) * kStH;
        tile_compute(stg, stg + kAstH, wm, wn, acc);
    }

    // Epilogue: stage 128x128 fp32 (stride 132) in smem, add bias, stores.
    __syncthreads();
    float* stage = reinterpret_cast<float*>(smem_raw);
#pragma unroll
    for (int i = 0; i < 2; i++)
#pragma unroll
        for (int j = 0; j < 4; j++)
            wmma::store_matrix_sync(stage + (wm * 32 + i * 16) * 132 + wn * 64 + j * 16,
                                    acc[i][j], 132, wmma::mem_row_major);
    __syncthreads();

    float* O = out + (size_t)mat * kM * kFO + (size_t)m0 * kFO + n0;
#pragma unroll
    for (int i = 0; i < 16; i++) {
        const int id = t + i * 256;
        const int r = id >> 5, c4 = (id & 31) * 4;
        float4 v = *reinterpret_cast<const float4*>(stage + r * 132 + c4);
        const float4 bv = *reinterpret_cast<const float4*>(bias + n0 + c4);
        v.x += bv.x; v.y += bv.y; v.z += bv.z; v.w += bv.w;
        *reinterpret_cast<float4*>(O + (size_t)r * kFO + c4) = v;
    }
}

// ---------------------------------------------------------------------------
// kernel_launch
// ---------------------------------------------------------------------------
extern "C" void kernel_launch(void* const* d_in, const int* in_sizes, int n_in,
                              void* d_out, int out_size)
{
    const float* s   = (const float*)d_in[0];
    const float* Wg1 = (const float*)d_in[1];
    const float* bg1 = (const float*)d_in[2];
    const float* Wg2 = (const float*)d_in[3];
    const float* bg2 = (const float*)d_in[4];
    const float* W1  = (const float*)d_in[5];
    const float* b1  = (const float*)d_in[6];
    const float* W2  = (const float*)d_in[7];
    const float* b2  = (const float*)d_in[8];
    const float* WA  = (const float*)d_in[9];
    const float* bA  = (const float*)d_in[10];
    const float* WB  = (const float*)d_in[11];
    const float* bB  = (const float*)d_in[12];
    float* out = (float*)d_out;

    cudaFuncSetAttribute(k_gemm_eo,  cudaFuncAttributeMaxDynamicSharedMemorySize, kSmemGemm);
    cudaFuncSetAttribute(k_gemm_out, cudaFuncAttributeMaxDynamicSharedMemorySize, kSmemGemm);

    k_fused<<<kFusedBlocks, 256>>>(s, W1, b1, Wg1, bg1, W2);
    k_gate<<<1, 1024>>>(Wg2, bg2);
    k_gemm_eo<<<dim3(kH2 / 128, 2, 2 * kNE + kCvtZ), 256, kSmemGemm>>>(W1, WA, WB);
    k_z<<<(kM * kH2) / 256, 256>>>(b2);
    k_gemm_out<<<dim3(kFO / 128, 2, 2), 256, kSmemGemm>>>(bA, bB, out);
}

// round 15
// speedup vs baseline: 1.1707x; 1.0101x over previous
#include <cuda_runtime.h>
#include <cuda_fp16.h>
#include <cstdint>
#include <mma.h>

using namespace nvcuda;

// ---------------------------------------------------------------------------
// MoE HyperModel, round 14: GEMMs -> 128-thread CTAs, warp tile 64x64
// (fragment-loads/mma 0.75 -> 0.5), block tile 128x128, 3-stage ring,
// 2 CTAs/SM. Convert piggyback + fused base kept from R13.
// ---------------------------------------------------------------------------

namespace {
constexpr int kEMB = 1024;
constexpr int kCTX = 32;
constexpr int kNE  = 16;
constexpr int kH1  = 2048;
constexpr int kH2  = 512;
constexpr int kB   = 8;
constexpr int kM   = kCTX * kB;     // 256
constexpr int kFO  = 16384;
constexpr int kW1R = kEMB + kCTX;   // 1056

constexpr int kLDAh = 72;    // smem A stride (halves): 128 rows x 64 k (+pad)
constexpr int kLDBh = 136;   // smem B stride (halves): 64 rows x 128 n (+pad)
constexpr int kAstH = 128 * kLDAh;        // 9216 halves
constexpr int kBstH = 64 * kLDBh;         // 8704 halves
constexpr int kStH  = kAstH + kBstH;      // 17920 halves
constexpr int kSmemGemm = 3 * kStH * 2;   // 107520 bytes (2 CTAs/SM)

// k_fused block ranges (base + W2 convert only)
constexpr int kBaseBlocks = (kH1 / 256) * (kNE + 1);            // 136
constexpr int kW2Elems = kNE * kH1 * kH2;                       // 16,777,216
constexpr int kWOElems = kH2 * kFO;                             //  8,388,608
constexpr int kW2Blocks = kW2Elems / 2048;                      // 8192
constexpr int kFusedBlocks = kBaseBlocks + kW2Blocks;           // 8328

// eo-launch convert role: 1024 blocks x 16384 elems cover WA+WB
constexpr int kCvtZ = 128;
}

// Scratch (static device arrays -- allocation-free).
__device__ float  g_g1[kB * kH1];
__device__ float  g_w[kB * kNE];
__device__ float  g_base[kNE * kB * kH1];
__device__ float  g_eo2[(size_t)2 * kNE * kM * kH2];   // split-K partials
__device__ __half g_zh[kM * kH2];                      // z in fp16
__device__ __half g_W2h[(size_t)kW2Elems];             // 33.5 MB
__device__ __half g_WAh[(size_t)kWOElems];             // 16.8 MB
__device__ __half g_WBh[(size_t)kWOElems];             // 16.8 MB

// --------------------------- cp.async helpers ------------------------------
__device__ __forceinline__ void cp_async16(void* smem_dst, const void* gmem_src) {
    unsigned int s = (unsigned int)__cvta_generic_to_shared(smem_dst);
    asm volatile("cp.async.cg.shared.global [%0], [%1], 16;\n" :: "r"(s), "l"(gmem_src));
}
__device__ __forceinline__ void cp_commit() {
    asm volatile("cp.async.commit_group;\n");
}
template <int N>
__device__ __forceinline__ void cp_wait() {
    asm volatile("cp.async.wait_group %0;\n" :: "n"(N));
}

// --------------------------- convert helper --------------------------------
__device__ __forceinline__ void cvt8(const float* __restrict__ src,
                                     __half* __restrict__ dst, size_t i)
{
    const float4 a = *reinterpret_cast<const float4*>(src + i);
    const float4 b = *reinterpret_cast<const float4*>(src + i + 4);
    __half2 h0 = __floats2half2_rn(a.x, a.y);
    __half2 h1 = __floats2half2_rn(a.z, a.w);
    __half2 h2 = __floats2half2_rn(b.x, b.y);
    __half2 h3 = __floats2half2_rn(b.z, b.w);
    uint4 v;
    v.x = *reinterpret_cast<unsigned*>(&h0);
    v.y = *reinterpret_cast<unsigned*>(&h1);
    v.z = *reinterpret_cast<unsigned*>(&h2);
    v.w = *reinterpret_cast<unsigned*>(&h3);
    *reinterpret_cast<uint4*>(dst + i) = v;
}

// --------------------------- stage loaders (128 threads) -------------------
// B: 64 k-rows x 128 n halves via cp.async (pre-offset to n0). 8 chunks/thr.
__device__ __forceinline__ void load_B(__half* Bs, const __half* B, int ldb,
                                       int kt, int t)
{
#pragma unroll
    for (int i = 0; i < 8; i++) {
        const int id = t + i * 128;
        const int r = id >> 4, c8 = (id & 15) * 8;
        cp_async16(Bs + r * kLDBh + c8, B + (size_t)(kt + r) * ldb + c8);
    }
}
// A (out GEMM): 128 rows x 64 k halves via cp.async (pre-offset to m0). 8/thr.
__device__ __forceinline__ void load_A_cp(__half* As, const __half* A, int lda,
                                          int kt, int t)
{
#pragma unroll
    for (int i = 0; i < 8; i++) {
        const int id = t + i * 128;
        const int m = id >> 3, kc = (id & 7) * 8;
        cp_async16(As + m * kLDAh + kc, A + (size_t)m * lda + kt + kc);
    }
}
// A (eo GEMM, fused h): half( w[b] * relu(base[b][k] + W1c[c][k]) ), STS.
__device__ __forceinline__ void load_A_eo(__half* As,
                                          const float* base_e, const float* w1c_e,
                                          const float* ws, int m0, int kt, int t)
{
#pragma unroll
    for (int i = 0; i < 8; i++) {
        const int id = t + i * 128;
        const int ml = id >> 3, kc = (id & 7) * 8;
        const int m = m0 + ml;
        const int b = m & 7, c = m >> 3;
        const float* bp = base_e + (size_t)b * kH1 + kt + kc;
        const float* wp = w1c_e  + (size_t)c * kH1 + kt + kc;
        const float4 b0 = *reinterpret_cast<const float4*>(bp);
        const float4 b1 = *reinterpret_cast<const float4*>(bp + 4);
        const float4 w0 = *reinterpret_cast<const float4*>(wp);
        const float4 w1 = *reinterpret_cast<const float4*>(wp + 4);
        const float w = ws[b];
        __half2 h0 = __floats2half2_rn(w * fmaxf(b0.x + w0.x, 0.f), w * fmaxf(b0.y + w0.y, 0.f));
        __half2 h1 = __floats2half2_rn(w * fmaxf(b0.z + w0.z, 0.f), w * fmaxf(b0.w + w0.w, 0.f));
        __half2 h2 = __floats2half2_rn(w * fmaxf(b1.x + w1.x, 0.f), w * fmaxf(b1.y + w1.y, 0.f));
        __half2 h3 = __floats2half2_rn(w * fmaxf(b1.z + w1.z, 0.f), w * fmaxf(b1.w + w1.w, 0.f));
        uint4 v;
        v.x = *reinterpret_cast<unsigned*>(&h0);
        v.y = *reinterpret_cast<unsigned*>(&h1);
        v.z = *reinterpret_cast<unsigned*>(&h2);
        v.w = *reinterpret_cast<unsigned*>(&h3);
        *reinterpret_cast<uint4*>(As + ml * kLDAh + kc) = v;
    }
}

// --------------------------- compute: warp 64x64, k-tile 64 ----------------
// 4 warps: wm = warp>>1 (2 m-slots of 64), wn = warp&1 (2 n-slots of 64).
__device__ __forceinline__ void tile_compute(
    const __half* As, const __half* Bs, int wm, int wn,
    wmma::fragment<wmma::accumulator, 16, 16, 16, float> (&acc)[4][4])
{
#pragma unroll
    for (int kk = 0; kk < 4; kk++) {
        wmma::fragment<wmma::matrix_b, 16, 16, 16, __half, wmma::row_major> bf[4];
#pragma unroll
        for (int j = 0; j < 4; j++)
            wmma::load_matrix_sync(bf[j], Bs + (kk * 16) * kLDBh + wn * 64 + j * 16, kLDBh);
#pragma unroll
        for (int i = 0; i < 4; i++) {
            wmma::fragment<wmma::matrix_a, 16, 16, 16, __half, wmma::row_major> af;
            wmma::load_matrix_sync(af, As + (wm * 64 + i * 16) * kLDAh + kk * 16, kLDAh);
#pragma unroll
            for (int j = 0; j < 4; j++)
                wmma::mma_sync(acc[i][j], af, bf[j], acc[i][j]);
        }
    }
}

// ---------------------------------------------------------------------------
// k_fused: base role (136 blocks) + W2 convert role (8192 blocks). 256 thr.
// ---------------------------------------------------------------------------
__global__ __launch_bounds__(256) void k_fused(
    const float* __restrict__ s,
    const float* __restrict__ W1, const float* __restrict__ b1,
    const float* __restrict__ Wg1, const float* __restrict__ bg1,
    const float* __restrict__ W2)
{
    const int bid = blockIdx.x;
    const int t = threadIdx.x;

    if (bid >= kBaseBlocks) {
        const int cb = bid - kBaseBlocks;
        cvt8(W2, g_W2h, ((size_t)cb * 256 + t) * 8);
        return;
    }

    // ---- base role ----
    __shared__ float sh[kB * kEMB];
    const int e = bid >> 3;
    const int jt = bid & 7;
    const int q = t & 63;
    const int slice = t >> 6;
    const int j = jt * 256 + q * 4;

    for (int i = t; i < kB * kEMB; i += 256) sh[i] = s[i];
    __syncthreads();

    const float* __restrict__ W = (e < kNE) ? (W1 + (size_t)e * kW1R * kH1) : Wg1;

    float acc[kB][4];
#pragma unroll
    for (int b = 0; b < kB; b++)
#pragma unroll
        for (int c = 0; c < 4; c++) acc[b][c] = 0.f;

    const int i0 = slice * 256;
#pragma unroll 8
    for (int i = i0; i < i0 + 256; i++) {
        const float4 wv = *reinterpret_cast<const float4*>(W + (size_t)i * kH1 + j);
#pragma unroll
        for (int b = 0; b < kB; b++) {
            const float sv = sh[b * kEMB + i];
            acc[b][0] += sv * wv.x;
            acc[b][1] += sv * wv.y;
            acc[b][2] += sv * wv.z;
            acc[b][3] += sv * wv.w;
        }
    }

    __syncthreads();
    if (slice > 0) {
#pragma unroll
        for (int b = 0; b < kB; b++)
#pragma unroll
            for (int c = 0; c < 4; c++)
                sh[(b * 4 + c) * 192 + (slice - 1) * 64 + q] = acc[b][c];
    }
    __syncthreads();
    if (slice == 0) {
#pragma unroll
        for (int sl = 0; sl < 3; sl++)
#pragma unroll
            for (int b = 0; b < kB; b++)
#pragma unroll
                for (int c = 0; c < 4; c++)
                    acc[b][c] += sh[(b * 4 + c) * 192 + sl * 64 + q];

        if (e < kNE) {
            const float4 bias = *reinterpret_cast<const float4*>(b1 + e * kH1 + j);
#pragma unroll
            for (int b = 0; b < kB; b++) {
                float4 o;
                o.x = acc[b][0] + bias.x; o.y = acc[b][1] + bias.y;
                o.z = acc[b][2] + bias.z; o.w = acc[b][3] + bias.w;
                *reinterpret_cast<float4*>(&g_base[((size_t)e * kB + b) * kH1 + j]) = o;
            }
        } else {
            const float4 bias = *reinterpret_cast<const float4*>(bg1 + j);
#pragma unroll
            for (int b = 0; b < kB; b++) {
                float4 o;
                o.x = fmaxf(acc[b][0] + bias.x, 0.f);
                o.y = fmaxf(acc[b][1] + bias.y, 0.f);
                o.z = fmaxf(acc[b][2] + bias.z, 0.f);
                o.w = fmaxf(acc[b][3] + bias.w, 0.f);
                *reinterpret_cast<float4*>(&g_g1[b * kH1 + j]) = o;
            }
        }
    }
}

// ---------------------------------------------------------------------------
// k_gate
// ---------------------------------------------------------------------------
__global__ __launch_bounds__(1024) void k_gate(
    const float* __restrict__ Wg2, const float* __restrict__ bg2)
{
    __shared__ float red[1024];
    const int t = threadIdx.x;
    const int b = t >> 7;
    const int rem = t & 127;
    const int kc = rem >> 4;
    const int x = rem & 15;

    float acc = 0.f;
    const int j0 = kc * 256;
#pragma unroll 4
    for (int j = j0; j < j0 + 256; j++)
        acc += g_g1[b * kH1 + j] * Wg2[j * kNE + x];
    red[t] = acc;
    __syncthreads();

    if (t < 128) {
        const int bb = t >> 4;
        const int xx = t & 15;
        float a = bg2[xx];
#pragma unroll
        for (int k = 0; k < 8; k++) a += red[bb * 128 + k * 16 + xx];

        float mx = a;
#pragma unroll
        for (int o = 8; o >= 1; o >>= 1)
            mx = fmaxf(mx, __shfl_xor_sync(0xffffffffu, mx, o, 16));
        const float ev = expf(a - mx);
        float sm = ev;
#pragma unroll
        for (int o = 8; o >= 1; o >>= 1)
            sm += __shfl_xor_sync(0xffffffffu, sm, o, 16);

        g_w[bb * kNE + xx] = ev / sm;
    }
}

// ---------------------------------------------------------------------------
// k_gemm_eo: GEMM role (z < 32): fused-h split-K fp16 GEMM, tile 128x128,
// 128 threads, warp 64x64, 2 CTAs/SM. Convert role (z >= 32): WA/WB cvt.
// Grid: (4, 2, 32 + kCvtZ).
// ---------------------------------------------------------------------------
__global__ __launch_bounds__(128, 2) void k_gemm_eo(
    const float* __restrict__ W1,
    const float* __restrict__ WA, const float* __restrict__ WB)
{
    extern __shared__ __align__(16) char smem_raw[];
    __half* smem = reinterpret_cast<__half*>(smem_raw);
    __shared__ float ws[kB];

    const int t = threadIdx.x;
    const int zz = blockIdx.z;

    if (zz >= 2 * kNE) {
        // ---- convert role: WA then WB, 16384 elems per block (128 thr) ----
        const int cb = (zz - 2 * kNE) * 8 + blockIdx.y * 4 + blockIdx.x;  // 0..1023
        const float* src = (cb < 512) ? WA : WB;
        __half* dst      = (cb < 512) ? g_WAh : g_WBh;
        const size_t base = (size_t)(cb & 511) * 16384;
#pragma unroll
        for (int i = 0; i < 16; i++)
            cvt8(src, dst, base + (size_t)i * 1024 + t * 8);
        return;
    }

    const int warp = t >> 5;
    const int wm = warp >> 1;   // 0..1
    const int wn = warp & 1;    // 0..1
    const int e = zz >> 1, kh = zz & 1;
    const int m0 = blockIdx.y * 128;
    const int n0 = blockIdx.x * 128;

    if (t < kB) ws[t] = g_w[t * kNE + e];

    const float* base_e = g_base + (size_t)e * kB * kH1 + kh * 1024;
    const float* w1c_e  = W1 + ((size_t)e * kW1R + kEMB) * kH1 + kh * 1024;
    const __half* B     = g_W2h + (size_t)e * kH1 * kH2 + (size_t)(kh * 1024) * kH2 + n0;

    wmma::fragment<wmma::accumulator, 16, 16, 16, float> acc[4][4];
#pragma unroll
    for (int i = 0; i < 4; i++)
#pragma unroll
        for (int j = 0; j < 4; j++) wmma::fill_fragment(acc[i][j], 0.f);

    __syncthreads();   // ws visible

    constexpr int NT = 1024 / 64;   // 16
    load_B(smem + kAstH, B, kH2, 0, t);
    cp_commit();
    load_A_eo(smem, base_e, w1c_e, ws, m0, 0, t);
    load_B(smem + kStH + kAstH, B, kH2, 64, t);
    cp_commit();
    load_A_eo(smem + kStH, base_e, w1c_e, ws, m0, 64, t);
    __syncthreads();

    for (int it = 0; it < NT; it++) {
        if (it + 1 < NT) cp_wait<1>(); else cp_wait<0>();
        __syncthreads();
        if (it + 2 < NT) {
            __half* nxt = smem + ((it + 2) % 3) * kStH;
            load_B(nxt + kAstH, B, kH2, (it + 2) * 64, t);
            cp_commit();
            load_A_eo(nxt, base_e, w1c_e, ws, m0, (it + 2) * 64, t);
        }
        const __half* stg = smem + (it % 3) * kStH;
        tile_compute(stg, stg + kAstH, wm, wn, acc);
    }

    float* O = g_eo2 + (size_t)zz * kM * kH2 + (size_t)m0 * kH2 + n0;
#pragma unroll
    for (int i = 0; i < 4; i++)
#pragma unroll
        for (int j = 0; j < 4; j++)
            wmma::store_matrix_sync(O + (size_t)(wm * 64 + i * 16) * kH2 + wn * 64 + j * 16,
                                    acc[i][j], kH2, wmma::mem_row_major);
}

// ---------------------------------------------------------------------------
// k_z: z = half( sum over 32 partial slabs + sum_e w[b,e]*b2[e] ).
// ---------------------------------------------------------------------------
__global__ __launch_bounds__(256) void k_z(const float* __restrict__ b2)
{
    const int idx = blockIdx.x * 256 + threadIdx.x;
    const int n = idx & (kH2 - 1);
    const int m = idx >> 9;
    const int b = m & 7;

    float acc = 0.f;
#pragma unroll
    for (int p = 0; p < 2 * kNE; p++)
        acc += g_eo2[(size_t)p * (kM * kH2) + idx];
#pragma unroll
    for (int e = 0; e < kNE; e++)
        acc += g_w[b * kNE + e] * b2[e * kH2 + n];
    g_zh[idx] = __float2half_rn(acc);
}

// ---------------------------------------------------------------------------
// k_gemm_out: z(256x512 fp16) @ {WAh,WBh}(512x16384 fp16) + bias -> out f32.
// Tile 128x128, 128 threads, warp 64x64, 2 CTAs/SM. Grid (128, 2, 2).
// ---------------------------------------------------------------------------
__global__ __launch_bounds__(128, 2) void k_gemm_out(
    const float* __restrict__ bA, const float* __restrict__ bB,
    float* __restrict__ out)
{
    extern __shared__ __align__(16) char smem_raw[];
    __half* smem = reinterpret_cast<__half*>(smem_raw);

    const int t = threadIdx.x;
    const int warp = t >> 5;
    const int wm = warp >> 1;
    const int wn = warp & 1;
    const int mat = blockIdx.z;
    const int m0 = blockIdx.y * 128;
    const int n0 = blockIdx.x * 128;

    const __half* Bw = (mat ? g_WBh : g_WAh) + n0;
    const float* bias = mat ? bB : bA;
    const __half* A = g_zh + (size_t)m0 * kH2;

    wmma::fragment<wmma::accumulator, 16, 16, 16, float> acc[4][4];
#pragma unroll
    for (int i = 0; i < 4; i++)
#pragma unroll
        for (int j = 0; j < 4; j++) wmma::fill_fragment(acc[i][j], 0.f);

    constexpr int NT = kH2 / 64;   // 8
    load_A_cp(smem, A, kH2, 0, t);
    load_B(smem + kAstH, Bw, kFO, 0, t);
    cp_commit();
    load_A_cp(smem + kStH, A, kH2, 64, t);
    load_B(smem + kStH + kAstH, Bw, kFO, 64, t);
    cp_commit();

    for (int it = 0; it < NT; it++) {
        if (it + 1 < NT) cp_wait<1>(); else cp_wait<0>();
        __syncthreads();
        if (it + 2 < NT) {
            __half* nxt = smem + ((it + 2) % 3) * kStH;
            load_A_cp(nxt, A, kH2, (it + 2) * 64, t);
            load_B(nxt + kAstH, Bw, kFO, (it + 2) * 64, t);
            cp_commit();
        }
        const __half* stg = smem + (it % 3) * kStH;
        tile_compute(stg, stg + kAstH, wm, wn, acc);
    }

    // Epilogue: stage 128x128 fp32 (stride 132) in smem, add bias, stores.
    __syncthreads();
    float* stage = reinterpret_cast<float*>(smem_raw);   // 67584 B <= 107520
#pragma unroll
    for (int i = 0; i < 4; i++)
#pragma unroll
        for (int j = 0; j < 4; j++)
            wmma::store_matrix_sync(stage + (wm * 64 + i * 16) * 132 + wn * 64 + j * 16,
                                    acc[i][j], 132, wmma::mem_row_major);
    __syncthreads();

    float* O = out + (size_t)mat * kM * kFO + (size_t)m0 * kFO + n0;
#pragma unroll
    for (int i = 0; i < 32; i++) {
        const int id = t + i * 128;
        const int r = id >> 5, c4 = (id & 31) * 4;
        float4 v = *reinterpret_cast<const float4*>(stage + r * 132 + c4);
        const float4 bv = *reinterpret_cast<const float4*>(bias + n0 + c4);
        v.x += bv.x; v.y += bv.y; v.z += bv.z; v.w += bv.w;
        *reinterpret_cast<float4*>(O + (size_t)r * kFO + c4) = v;
    }
}

// ---------------------------------------------------------------------------
// kernel_launch
// ---------------------------------------------------------------------------
extern "C" void kernel_launch(void* const* d_in, const int* in_sizes, int n_in,
                              void* d_out, int out_size)
{
    const float* s   = (const float*)d_in[0];
    const float* Wg1 = (const float*)d_in[1];
    const float* bg1 = (const float*)d_in[2];
    const float* Wg2 = (const float*)d_in[3];
    const float* bg2 = (const float*)d_in[4];
    const float* W1  = (const float*)d_in[5];
    const float* b1  = (const float*)d_in[6];
    const float* W2  = (const float*)d_in[7];
    const float* b2  = (const float*)d_in[8];
    const float* WA  = (const float*)d_in[9];
    const float* bA  = (const float*)d_in[10];
    const float* WB  = (const float*)d_in[11];
    const float* bB  = (const float*)d_in[12];
    float* out = (float*)d_out;

    cudaFuncSetAttribute(k_gemm_eo,  cudaFuncAttributeMaxDynamicSharedMemorySize, kSmemGemm);
    cudaFuncSetAttribute(k_gemm_out, cudaFuncAttributeMaxDynamicSharedMemorySize, kSmemGemm);

    k_fused<<<kFusedBlocks, 256>>>(s, W1, b1, Wg1, bg1, W2);
    k_gate<<<1, 1024>>>(Wg2, bg2);
    k_gemm_eo<<<dim3(kH2 / 128, 2, 2 * kNE + kCvtZ), 128, kSmemGemm>>>(W1, WA, WB);
    k_z<<<(kM * kH2) / 256, 256>>>(b2);
    k_gemm_out<<<dim3(kFO / 128, 2, 2), 128, kSmemGemm>>>(bA, bB, out);
}